// round 16
// baseline (speedup 1.0000x reference)
#include <cuda_runtime.h>
#include <math.h>

// Problem constants (fixed by dataset): B=32, S=1024, T=64, ENC=768, HID=256
#define BB  32
#define TT  64
#define ENC 768
#define HID 256

// Scratch (no allocations allowed). float2 => 8B alignment for paired loads.
__device__ float2 g_e2[BB * TT / 2];   // e[b,k] at ((float*)g_e2)[b*TT+k]

// LSE-state combine: (m,s) ⊕ (m2,s2). Identity = (-1e30, 0). No NaNs: __expf
// of very-negative underflows to 0 (mirrors the reference's -1e30 mask).
__device__ __forceinline__ void lse_comb(float& m, float& s, float m2, float s2) {
    float nm = fmaxf(m, m2);
    s = s * __expf(m - nm) + s2 * __expf(m2 - nm);
    m = nm;
}

// ---------------------------------------------------------------------------
// Algebra: scores[b,j,k] = a[b,j] + e[b,k] + fc_b is rank-1 separable, so
//   loss_j = logsumexp_{k=j+1..len-1}(e[b,k]) - e[b,j+1]
// The LSTM path (a[j]) and fc_b cancel exactly. Summing over k = j+1:
//   loss_b = sum_{k=1..L-1} [ LSE(e[k..L-1]) - e[k] ].
//
// Two kernels (measured: graph total ≈ sum of kernel durs; the fused variant's
// device-wide threadfence arrival cost ~8µs and is gone):
//   K1: warp per (b,k): gathered 768-dot e[b,k]          (~2.1 µs measured)
//   K2: ONE block: 8 warps, warp w scans batches {w,w+8,w+16,w+24} with a
//       5-level shfl suffix-LSE (2 positions/lane); fixed-order reduce.
// ---------------------------------------------------------------------------

__global__ void __launch_bounds__(256) e_kernel(const float* __restrict__ enc,
                                                const float* __restrict__ fc_w,
                                                const int*   __restrict__ ids,
                                                const int*   __restrict__ lens,
                                                int S) {
    int w    = (blockIdx.x * blockDim.x + threadIdx.x) >> 5;  // 0..2047
    int lane = threadIdx.x & 31;
    if (w >= BB * TT) return;
    int b = w >> 6;
    int k = w & (TT - 1);

    float e = 0.0f;
    int len = __ldg(&lens[b]);
    if (k >= 1 && k < len) {               // k=0 never appears in any suffix
        int row = __ldg(&ids[b * TT + k]);
        const float4* x  = (const float4*)(enc + ((long long)b * S + row) * ENC);
        const float4* wv = (const float4*)(fc_w + HID);
        float4 xv[6];
        #pragma unroll
        for (int i = 0; i < 6; ++i)        // all 6 gathered loads in flight
            xv[i] = __ldg(&x[lane + 32 * i]);
        float acc = 0.0f;
        #pragma unroll
        for (int i = 0; i < 6; ++i) {
            float4 ww = __ldg(&wv[lane + 32 * i]);
            acc += xv[i].x * ww.x + xv[i].y * ww.y
                 + xv[i].z * ww.z + xv[i].w * ww.w;
        }
        #pragma unroll
        for (int o = 16; o; o >>= 1)
            acc += __shfl_down_sync(0xffffffffu, acc, o);
        e = acc;
    }
    if (lane == 0) ((float*)g_e2)[w] = e;  // stale values for invalid k are
                                           // never consumed (gated in K2)
}

__global__ void __launch_bounds__(256) scan_final_kernel(const int* __restrict__ lens,
                                                         float* __restrict__ out) {
    __shared__ float sh_loss[BB];
    int wid  = threadIdx.x >> 5;           // 0..7
    int lane = threadIdx.x & 31;

    for (int b = wid; b < BB; b += 8) {
        int L = __ldg(&lens[b]);           // L in [2, 64]
        float2 vv = g_e2[b * 32 + lane];   // coalesced 256B/warp, L2-hot
        float v0 = vv.x, v1 = vv.y;
        int  k0 = 2 * lane, k1 = 2 * lane + 1;
        bool val0 = (k0 >= 1) & (k0 < L);
        bool val1 = (k1 < L);              // k1 >= 1 always

        float m0 = val0 ? v0 : -1e30f, s0 = val0 ? 1.0f : 0.0f;
        float m1 = val1 ? v1 : -1e30f, s1 = val1 ? 1.0f : 0.0f;

        // lane-local aggregate = e(k0) ⊕ e(k1)
        float am = m0, as = s0;
        lse_comb(am, as, m1, s1);

        // inclusive suffix scan over lane aggregates (Hillis–Steele, rightward)
        float sm = am, ss = as;
        #pragma unroll
        for (int o = 1; o < 32; o <<= 1) {
            float tm = __shfl_down_sync(0xffffffffu, sm, o);
            float ts = __shfl_down_sync(0xffffffffu, ss, o);
            if (lane + o < 32) lse_comb(sm, ss, tm, ts);
        }
        // exclusive suffix (lanes > l)
        float em = __shfl_down_sync(0xffffffffu, sm, 1);
        float es = __shfl_down_sync(0xffffffffu, ss, 1);
        if (lane == 31) { em = -1e30f; es = 0.0f; }

        // suffix state at k0 = inclusive(l); at k1 = e(k1) ⊕ exclusive(l)
        float c1m = m1, c1s = s1;
        lse_comb(c1m, c1s, em, es);

        float t = 0.0f;
        if (val0) t += (sm  + __logf(ss))  - v0;   // term for k0 (s >= 1)
        if (val1) t += (c1m + __logf(c1s)) - v1;   // term for k1 (s >= 1)
        #pragma unroll
        for (int o = 16; o; o >>= 1)
            t += __shfl_down_sync(0xffffffffu, t, o);
        if (lane == 0) sh_loss[b] = t;
    }
    __syncthreads();

    // Fixed-order final reduction (deterministic)
    if (threadIdx.x < 32) {
        float l = sh_loss[threadIdx.x];
        float c = (float)(__ldg(&lens[threadIdx.x]) - 1);
        #pragma unroll
        for (int o = 16; o; o >>= 1) {
            l += __shfl_down_sync(0xffffffffu, l, o);
            c += __shfl_down_sync(0xffffffffu, c, o);
        }
        if (threadIdx.x == 0) out[0] = l / c;
    }
}

// ---------------------------------------------------------------------------
// Inputs (metadata order): 0 encoder_output f32 [B,S,ENC], 1 W_ih, 2 W_hh,
// 3 b_ih, 4 b_hh, 5 fc_w f32 [1, ENC+HID], 6 fc_b, 7 his_turn_end_ids i32
// [B,T], 8 turn_lengths i32 [B].  Output: 1 float.
// W_ih/W_hh/biases/fc_b cancel out of the loss and are never read.
// ---------------------------------------------------------------------------
extern "C" void kernel_launch(void* const* d_in, const int* in_sizes, int n_in,
                              void* d_out, int out_size) {
    const float* enc  = (const float*)d_in[0];
    const float* fc_w = (const float*)d_in[5];
    const int*   ids  = (const int*)d_in[7];
    const int*   lens = (const int*)d_in[8];
    int S = in_sizes[0] / (BB * ENC);   // row stride of encoder_output

    e_kernel<<<256, 256>>>(enc, fc_w, ids, lens, S);
    scan_final_kernel<<<1, 256>>>(lens, (float*)d_out);
}

// round 17
// speedup vs baseline: 1.0208x; 1.0208x over previous
#include <cuda_runtime.h>
#include <math.h>

// Problem constants (fixed by dataset): B=32, S=1024, T=64, ENC=768, HID=256
#define BB  32
#define TT  64
#define ENC 768
#define HID 256

// Scratch (no allocations allowed). float2 => 8B alignment for paired loads.
__device__ float2 g_e2[BB * TT / 2];   // e[b,k] at ((float*)g_e2)[b*TT+k]

// LSE-state combine: (m,s) ⊕ (m2,s2). Identity = (-1e30, 0). No NaNs: __expf
// of very-negative underflows to 0 (mirrors the reference's -1e30 mask).
__device__ __forceinline__ void lse_comb(float& m, float& s, float m2, float s2) {
    float nm = fmaxf(m, m2);
    s = s * __expf(m - nm) + s2 * __expf(m2 - nm);
    m = nm;
}

// ---------------------------------------------------------------------------
// Algebra: scores[b,j,k] = a[b,j] + e[b,k] + fc_b is rank-1 separable, so
//   loss_j = logsumexp_{k=j+1..len-1}(e[b,k]) - e[b,j+1]
// The LSTM path (a[j]) and fc_b cancel exactly. Summing over k = j+1:
//   loss_b = sum_{k=1..L-1} [ LSE(e[k..L-1]) - e[k] ].
//
// Two kernels (measured: graph total ≈ sum of kernel durs; the fused variant's
// device-wide threadfence arrival cost ~8µs and is gone):
//   K1: warp per (b,k): gathered 768-dot e[b,k]          (~2.1 µs measured)
//   K2: ONE block: 8 warps, warp w scans batches {w,w+8,w+16,w+24} with a
//       5-level shfl suffix-LSE (2 positions/lane); fixed-order reduce.
// ---------------------------------------------------------------------------

__global__ void __launch_bounds__(256) e_kernel(const float* __restrict__ enc,
                                                const float* __restrict__ fc_w,
                                                const int*   __restrict__ ids,
                                                const int*   __restrict__ lens,
                                                int S) {
    int w    = (blockIdx.x * blockDim.x + threadIdx.x) >> 5;  // 0..2047
    int lane = threadIdx.x & 31;
    if (w >= BB * TT) return;
    int b = w >> 6;
    int k = w & (TT - 1);

    float e = 0.0f;
    int len = __ldg(&lens[b]);
    if (k >= 1 && k < len) {               // k=0 never appears in any suffix
        int row = __ldg(&ids[b * TT + k]);
        const float4* x  = (const float4*)(enc + ((long long)b * S + row) * ENC);
        const float4* wv = (const float4*)(fc_w + HID);
        float4 xv[6];
        #pragma unroll
        for (int i = 0; i < 6; ++i)        // all 6 gathered loads in flight
            xv[i] = __ldg(&x[lane + 32 * i]);
        float acc = 0.0f;
        #pragma unroll
        for (int i = 0; i < 6; ++i) {
            float4 ww = __ldg(&wv[lane + 32 * i]);
            acc += xv[i].x * ww.x + xv[i].y * ww.y
                 + xv[i].z * ww.z + xv[i].w * ww.w;
        }
        #pragma unroll
        for (int o = 16; o; o >>= 1)
            acc += __shfl_down_sync(0xffffffffu, acc, o);
        e = acc;
    }
    if (lane == 0) ((float*)g_e2)[w] = e;  // stale values for invalid k are
                                           // never consumed (gated in K2)
}

__global__ void __launch_bounds__(256) scan_final_kernel(const int* __restrict__ lens,
                                                         float* __restrict__ out) {
    __shared__ float sh_loss[BB];
    int wid  = threadIdx.x >> 5;           // 0..7
    int lane = threadIdx.x & 31;

    for (int b = wid; b < BB; b += 8) {
        int L = __ldg(&lens[b]);           // L in [2, 64]
        float2 vv = g_e2[b * 32 + lane];   // coalesced 256B/warp, L2-hot
        float v0 = vv.x, v1 = vv.y;
        int  k0 = 2 * lane, k1 = 2 * lane + 1;
        bool val0 = (k0 >= 1) & (k0 < L);
        bool val1 = (k1 < L);              // k1 >= 1 always

        float m0 = val0 ? v0 : -1e30f, s0 = val0 ? 1.0f : 0.0f;
        float m1 = val1 ? v1 : -1e30f, s1 = val1 ? 1.0f : 0.0f;

        // lane-local aggregate = e(k0) ⊕ e(k1)
        float am = m0, as = s0;
        lse_comb(am, as, m1, s1);

        // inclusive suffix scan over lane aggregates (Hillis–Steele, rightward)
        float sm = am, ss = as;
        #pragma unroll
        for (int o = 1; o < 32; o <<= 1) {
            float tm = __shfl_down_sync(0xffffffffu, sm, o);
            float ts = __shfl_down_sync(0xffffffffu, ss, o);
            if (lane + o < 32) lse_comb(sm, ss, tm, ts);
        }
        // exclusive suffix (lanes > l)
        float em = __shfl_down_sync(0xffffffffu, sm, 1);
        float es = __shfl_down_sync(0xffffffffu, ss, 1);
        if (lane == 31) { em = -1e30f; es = 0.0f; }

        // suffix state at k0 = inclusive(l); at k1 = e(k1) ⊕ exclusive(l)
        float c1m = m1, c1s = s1;
        lse_comb(c1m, c1s, em, es);

        float t = 0.0f;
        if (val0) t += (sm  + __logf(ss))  - v0;   // term for k0 (s >= 1)
        if (val1) t += (c1m + __logf(c1s)) - v1;   // term for k1 (s >= 1)
        #pragma unroll
        for (int o = 16; o; o >>= 1)
            t += __shfl_down_sync(0xffffffffu, t, o);
        if (lane == 0) sh_loss[b] = t;
    }
    __syncthreads();

    // Fixed-order final reduction (deterministic)
    if (threadIdx.x < 32) {
        float l = sh_loss[threadIdx.x];
        float c = (float)(__ldg(&lens[threadIdx.x]) - 1);
        #pragma unroll
        for (int o = 16; o; o >>= 1) {
            l += __shfl_down_sync(0xffffffffu, l, o);
            c += __shfl_down_sync(0xffffffffu, c, o);
        }
        if (threadIdx.x == 0) out[0] = l / c;
    }
}

// ---------------------------------------------------------------------------
// Inputs (metadata order): 0 encoder_output f32 [B,S,ENC], 1 W_ih, 2 W_hh,
// 3 b_ih, 4 b_hh, 5 fc_w f32 [1, ENC+HID], 6 fc_b, 7 his_turn_end_ids i32
// [B,T], 8 turn_lengths i32 [B].  Output: 1 float.
// W_ih/W_hh/biases/fc_b cancel out of the loss and are never read.
// ---------------------------------------------------------------------------
extern "C" void kernel_launch(void* const* d_in, const int* in_sizes, int n_in,
                              void* d_out, int out_size) {
    const float* enc  = (const float*)d_in[0];
    const float* fc_w = (const float*)d_in[5];
    const int*   ids  = (const int*)d_in[7];
    const int*   lens = (const int*)d_in[8];
    int S = in_sizes[0] / (BB * ENC);   // row stride of encoder_output

    e_kernel<<<256, 256>>>(enc, fc_w, ids, lens, S);
    scan_final_kernel<<<1, 256>>>(lens, (float*)d_out);
}